// round 1
// baseline (speedup 1.0000x reference)
#include <cuda_runtime.h>

namespace {
constexpr int B_ = 32, A_ = 3, S_ = 80, NC_ = 80;
constexpr int NCELLS = B_ * A_ * S_ * S_;   // 614400
constexpr float EPSF = 1e-7f;
constexpr float LSF  = 0.1f;
}

// Accumulators: 0 noobj_sum, 1 noobj_cnt, 2 box_sum, 3 obj_sum, 4 cls_sum, 5 obj_cnt
__device__ double g_acc[6];
__device__ int    g_obj_count;
__device__ int    g_obj_idx[NCELLS];

__global__ void k_init() {
    if (threadIdx.x < 6) g_acc[threadIdx.x] = 0.0;
    if (threadIdx.x == 0) g_obj_count = 0;
}

__device__ __forceinline__ float bce_logits(float z, float t) {
    // max(z,0) - z*t + log1p(exp(-|z|))
    return fmaxf(z, 0.0f) - z * t + log1pf(__expf(-fabsf(z)));
}

// Phase A: thread per cell. No-object BCE on objectness logit; compact object cells.
__global__ void __launch_bounds__(256) k_phaseA(const float* __restrict__ pred,
                                                const float* __restrict__ tgt) {
    const int i    = blockIdx.x * 256 + threadIdx.x;   // grid sized exactly
    const int lane = threadIdx.x & 31;
    const int wid  = threadIdx.x >> 5;

    float t0 = tgt[(size_t)i * 6];
    float nl = 0.0f;
    int   nn = 0;
    bool isobj = (t0 == 1.0f);
    if (t0 == 0.0f) {
        float z = pred[(size_t)i * 85];
        nl = bce_logits(z, 0.0f);
        nn = 1;
    }

    // Warp-aggregated append of object-cell indices
    unsigned m = __ballot_sync(0xffffffffu, isobj);
    if (m) {
        int leader = __ffs(m) - 1;
        int base = 0;
        if (lane == leader) base = atomicAdd(&g_obj_count, __popc(m));
        base = __shfl_sync(0xffffffffu, base, leader);
        if (isobj) g_obj_idx[base + __popc(m & ((1u << lane) - 1u))] = i;
    }

    // Reduce no-object partials
    #pragma unroll
    for (int o = 16; o; o >>= 1) {
        nl += __shfl_xor_sync(0xffffffffu, nl, o);
        nn += __shfl_xor_sync(0xffffffffu, nn, o);
    }
    __shared__ float s_nl[8];
    __shared__ int   s_nn[8];
    if (lane == 0) { s_nl[wid] = nl; s_nn[wid] = nn; }
    __syncthreads();
    if (threadIdx.x == 0) {
        float a = 0.0f; int c = 0;
        #pragma unroll
        for (int w = 0; w < 8; ++w) { a += s_nl[w]; c += s_nn[w]; }
        atomicAdd(&g_acc[0], (double)a);
        atomicAdd(&g_acc[1], (double)c);
    }
}

// Phase B: warp per object cell (grid-stride over compacted list).
__global__ void __launch_bounds__(256) k_phaseB(const float* __restrict__ pred,
                                                const float* __restrict__ tgt,
                                                const float* __restrict__ anchors) {
    const int lane  = threadIdx.x & 31;
    const int wib   = threadIdx.x >> 5;           // warp in block
    const int gwarp = blockIdx.x * 8 + wib;
    const int nwarp = gridDim.x * 8;
    const int nobj  = g_obj_count;

    float a_box = 0.0f, a_obj = 0.0f, a_cls = 0.0f;
    int   a_cnt = 0;

    for (int w = gwarp; w < nobj; w += nwarp) {
        int cell = g_obj_idx[w];
        const float* p = pred + (size_t)cell * 85;
        float v0 = p[lane];
        float v1 = p[lane + 32];
        float v2 = (lane < 21) ? p[lane + 64] : 0.0f;
        float tv = (lane < 6) ? tgt[(size_t)cell * 6 + lane] : 0.0f;
        float t1 = __shfl_sync(0xffffffffu, tv, 1);
        float t2 = __shfl_sync(0xffffffffu, tv, 2);
        float t3 = __shfl_sync(0xffffffffu, tv, 3);
        float t4 = __shfl_sync(0xffffffffu, tv, 4);
        float t5 = __shfl_sync(0xffffffffu, tv, 5);
        int tch = 5 + (int)t5;                    // target class channel in [5,84]

        // Fused log-softmax pieces: sum(exp), sum(logits), selected logit
        float se = 0.0f, sl = 0.0f, yv = 0.0f;
        if (lane >= 5) { se += __expf(v0); sl += v0; if (lane      == tch) yv += v0; }
        {               se += __expf(v1); sl += v1; if (lane + 32 == tch) yv += v1; }
        if (lane < 21) { se += __expf(v2); sl += v2; if (lane + 64 == tch) yv += v2; }
        #pragma unroll
        for (int o = 16; o; o >>= 1) {
            se += __shfl_xor_sync(0xffffffffu, se, o);
            sl += __shfl_xor_sync(0xffffffffu, sl, o);
            yv += __shfl_xor_sync(0xffffffffu, yv, o);
        }
        // ce = logS - (1-LS)*logp_y_raw - (LS/NC)*sum_logits   (M=0: logits are O(1))
        float ce = __logf(se) - (1.0f - LSF) * yv - (LSF / (float)NC_) * sl;

        float z0 = __shfl_sync(0xffffffffu, v0, 0);
        float z1 = __shfl_sync(0xffffffffu, v0, 1);
        float z2 = __shfl_sync(0xffffffffu, v0, 2);
        float z3 = __shfl_sync(0xffffffffu, v0, 3);
        float z4 = __shfl_sync(0xffffffffu, v0, 4);

        if (lane == 0) {
            int a = (cell / (S_ * S_)) % A_;
            float aw = anchors[a * 2 + 0];
            float ah = anchors[a * 2 + 1];
            float px = 1.0f / (1.0f + __expf(-z1));
            float py = 1.0f / (1.0f + __expf(-z2));
            float pw = __expf(z3) * aw;
            float ph = __expf(z4) * ah;
            // CIoU(pred=b1, target=b2)
            float x1a = px - pw * 0.5f, x1b = px + pw * 0.5f;
            float y1a = py - ph * 0.5f, y1b = py + ph * 0.5f;
            float x2a = t1 - t3 * 0.5f, x2b = t1 + t3 * 0.5f;
            float y2a = t2 - t4 * 0.5f, y2b = t2 + t4 * 0.5f;
            float iw = fmaxf(fminf(x1b, x2b) - fmaxf(x1a, x2a), 0.0f);
            float ih = fmaxf(fminf(y1b, y2b) - fmaxf(y1a, y2a), 0.0f);
            float inter = iw * ih;
            float uni = pw * ph + t3 * t4 - inter + EPSF;
            float iou = inter / uni;
            float cw  = fmaxf(x1b, x2b) - fminf(x1a, x2a);
            float chh = fmaxf(y1b, y2b) - fminf(y1a, y2a);
            float c2 = cw * cw + chh * chh + EPSF;
            float rho2 = (t1 - px) * (t1 - px) + (t2 - py) * (t2 - py);
            const float k4pi2 = 4.0f / (3.14159265358979323846f * 3.14159265358979323846f);
            float dat = atanf(t3 / (t4 + EPSF)) - atanf(pw / (ph + EPSF));
            float vv = k4pi2 * dat * dat;
            float alpha = vv / (1.0f - iou + vv + EPSF);
            float ciou = iou - rho2 / c2 - alpha * vv;
            a_box += 1.0f - ciou;
            // quirk: sigmoid fed INTO bce-with-logits, target=1
            float s0 = 1.0f / (1.0f + __expf(-z0));
            a_obj += bce_logits(s0, 1.0f);
            a_cls += ce;
            a_cnt += 1;
        }
    }

    __shared__ float s_box[8], s_obj[8], s_cls[8];
    __shared__ int   s_cnt[8];
    if (lane == 0) { s_box[wib] = a_box; s_obj[wib] = a_obj; s_cls[wib] = a_cls; s_cnt[wib] = a_cnt; }
    __syncthreads();
    if (threadIdx.x == 0) {
        float b = 0.0f, o = 0.0f, c = 0.0f; int n = 0;
        #pragma unroll
        for (int w2 = 0; w2 < 8; ++w2) { b += s_box[w2]; o += s_obj[w2]; c += s_cls[w2]; n += s_cnt[w2]; }
        if (n) {
            atomicAdd(&g_acc[2], (double)b);
            atomicAdd(&g_acc[3], (double)o);
            atomicAdd(&g_acc[4], (double)c);
            atomicAdd(&g_acc[5], (double)n);
        }
    }
}

__global__ void k_final(float* __restrict__ out) {
    double no_l = g_acc[0] / fmax(g_acc[1], 1.0);
    double den  = fmax(g_acc[5], 1.0);
    double box  = g_acc[2] / den;
    double objl = g_acc[3] / den;
    double cls  = g_acc[4] / den;
    out[0] = (float)(2.0 * box + objl + no_l + cls);
}

extern "C" void kernel_launch(void* const* d_in, const int* in_sizes, int n_in,
                              void* d_out, int out_size) {
    const float* pred = (const float*)d_in[0];
    const float* tgt  = (const float*)d_in[1];
    const float* anc  = (const float*)d_in[2];
    (void)in_sizes; (void)n_in; (void)out_size;

    k_init<<<1, 32>>>();
    k_phaseA<<<NCELLS / 256, 256>>>(pred, tgt);
    k_phaseB<<<296, 256>>>(pred, tgt, anc);
    k_final<<<1, 1>>>((float*)d_out);
}

// round 2
// speedup vs baseline: 1.3686x; 1.3686x over previous
#include <cuda_runtime.h>

namespace {
constexpr int B_ = 32, A_ = 3, S_ = 80, NC_ = 80;
constexpr int NCELLS = B_ * A_ * S_ * S_;   // 614400
constexpr int TPB = 256;
constexpr int NBLK = NCELLS / TPB;          // 2400
constexpr float EPSF = 1e-7f;
constexpr float LSF  = 0.1f;
}

// Accumulators: 0 noobj_sum, 1 noobj_cnt, 2 box_sum, 3 obj_sum, 4 cls_sum, 5 obj_cnt
__device__ double       g_acc[6];            // zero-init at module load; reset by last block
__device__ unsigned int g_done;              // ditto

__device__ __forceinline__ float bce0(float z) {   // BCE-with-logits, target = 0
    return fmaxf(z, 0.0f) + log1pf(__expf(-fabsf(z)));
}

__global__ void __launch_bounds__(TPB) k_fused(const float* __restrict__ pred,
                                               const float* __restrict__ tgt,
                                               const float* __restrict__ anchors,
                                               float* __restrict__ out) {
    __shared__ float s_tgt[TPB * 6];         // 6 KB staged target rows
    __shared__ int   s_obj[TPB];
    __shared__ int   s_cnt;
    __shared__ float s_nl[8];
    __shared__ int   s_nn[8];
    __shared__ float s_box[8], s_objl[8], s_cls[8];
    __shared__ int   s_bc[8];

    const int tid  = threadIdx.x;
    const int lane = tid & 31;
    const int wib  = tid >> 5;
    const int cell0 = blockIdx.x * TPB;

    if (tid == 0) s_cnt = 0;
    // coalesced float4 stage of 256 target rows (1536 floats = 384 float4)
    {
        const float4* gt4 = (const float4*)(tgt + (size_t)cell0 * 6);
        float4* st4 = (float4*)s_tgt;
        st4[tid]       = gt4[tid];
        if (tid < 128) st4[tid + 256] = gt4[tid + 256];
    }
    __syncthreads();

    // ---- Phase A: no-object BCE + block-local compaction ----
    const float t0 = s_tgt[tid * 6];
    const bool isno  = (t0 == 0.0f);
    const bool isobj = (t0 == 1.0f);
    float nl = 0.0f;
    if (isno) nl = bce0(pred[(size_t)(cell0 + tid) * 85]);
    int nn = __popc(__ballot_sync(0xffffffffu, isno));
    #pragma unroll
    for (int o = 16; o; o >>= 1) nl += __shfl_xor_sync(0xffffffffu, nl, o);
    if (lane == 0) { s_nl[wib] = nl; s_nn[wib] = nn; }

    unsigned m = __ballot_sync(0xffffffffu, isobj);
    if (m) {
        int leader = __ffs(m) - 1;
        int base = 0;
        if (lane == leader) base = atomicAdd(&s_cnt, __popc(m));
        base = __shfl_sync(0xffffffffu, base, leader);
        if (isobj) s_obj[base + __popc(m & ((1u << lane) - 1u))] = tid;
    }
    __syncthreads();

    // ---- Phase B: warp per object cell ----
    const int nobj = s_cnt;
    float a_box = 0.0f, a_obj = 0.0f, a_cls = 0.0f;
    int   a_cnt = 0;

    for (int w = wib; w < nobj; w += 8) {
        const int cl   = s_obj[w];
        const int cell = cell0 + cl;
        const float* p = pred + (size_t)cell * 85;
        float v0 = p[lane];
        float v1 = p[lane + 32];
        float v2 = (lane < 21) ? p[lane + 64] : 0.0f;

        const float t1 = s_tgt[cl * 6 + 1];
        const float t2 = s_tgt[cl * 6 + 2];
        const float t3 = s_tgt[cl * 6 + 3];
        const float t4 = s_tgt[cl * 6 + 4];
        const int  tch = 5 + (int)s_tgt[cl * 6 + 5];

        // fused label-smoothed CE: logΣe − (1−LS)·logit_y − (LS/NC)·Σlogits
        float se = 0.0f, sl = 0.0f, yv = 0.0f;
        if (lane >= 5) { se += __expf(v0); sl += v0; if (lane      == tch) yv += v0; }
        {               se += __expf(v1); sl += v1; if (lane + 32 == tch) yv += v1; }
        if (lane < 21) { se += __expf(v2); sl += v2; if (lane + 64 == tch) yv += v2; }
        #pragma unroll
        for (int o = 16; o; o >>= 1) {
            se += __shfl_xor_sync(0xffffffffu, se, o);
            sl += __shfl_xor_sync(0xffffffffu, sl, o);
            yv += __shfl_xor_sync(0xffffffffu, yv, o);
        }
        float ce = __logf(se) - (1.0f - LSF) * yv - (LSF / (float)NC_) * sl;

        float z0 = __shfl_sync(0xffffffffu, v0, 0);
        float z1 = __shfl_sync(0xffffffffu, v0, 1);
        float z2 = __shfl_sync(0xffffffffu, v0, 2);
        float z3 = __shfl_sync(0xffffffffu, v0, 3);
        float z4 = __shfl_sync(0xffffffffu, v0, 4);

        if (lane == 0) {
            const int a = (cell / (S_ * S_)) % A_;
            float aw = anchors[a * 2 + 0], ah = anchors[a * 2 + 1];
            float px = 1.0f / (1.0f + __expf(-z1));
            float py = 1.0f / (1.0f + __expf(-z2));
            float pw = __expf(z3) * aw;
            float ph = __expf(z4) * ah;
            float x1a = px - pw * 0.5f, x1b = px + pw * 0.5f;
            float y1a = py - ph * 0.5f, y1b = py + ph * 0.5f;
            float x2a = t1 - t3 * 0.5f, x2b = t1 + t3 * 0.5f;
            float y2a = t2 - t4 * 0.5f, y2b = t2 + t4 * 0.5f;
            float iw = fmaxf(fminf(x1b, x2b) - fmaxf(x1a, x2a), 0.0f);
            float ih = fmaxf(fminf(y1b, y2b) - fmaxf(y1a, y2a), 0.0f);
            float inter = iw * ih;
            float uni = pw * ph + t3 * t4 - inter + EPSF;
            float iou = inter / uni;
            float cw  = fmaxf(x1b, x2b) - fminf(x1a, x2a);
            float chh = fmaxf(y1b, y2b) - fminf(y1a, y2a);
            float c2  = cw * cw + chh * chh + EPSF;
            float rho2 = (t1 - px) * (t1 - px) + (t2 - py) * (t2 - py);
            const float k4pi2 = 4.0f / (3.14159265358979323846f * 3.14159265358979323846f);
            float dat = atanf(t3 / (t4 + EPSF)) - atanf(pw / (ph + EPSF));
            float vv = k4pi2 * dat * dat;
            float alpha = vv / (1.0f - iou + vv + EPSF);
            float ciou = iou - rho2 / c2 - alpha * vv;
            a_box += 1.0f - ciou;
            float s0 = 1.0f / (1.0f + __expf(-z0));          // quirk: sigmoid into BCE-logits
            a_obj += fmaxf(s0, 0.0f) - s0 + log1pf(__expf(-fabsf(s0)));
            a_cls += ce;
            a_cnt += 1;
        }
    }

    if (lane == 0) { s_box[wib] = a_box; s_objl[wib] = a_obj; s_cls[wib] = a_cls; s_bc[wib] = a_cnt; }
    __syncthreads();

    // ---- block totals -> global atomics, last block finalizes ----
    if (tid == 0) {
        float nlt = 0.0f, bx = 0.0f, ob = 0.0f, cs = 0.0f;
        int nnt = 0, bc = 0;
        #pragma unroll
        for (int w = 0; w < 8; ++w) {
            nlt += s_nl[w]; nnt += s_nn[w];
            bx += s_box[w]; ob += s_objl[w]; cs += s_cls[w]; bc += s_bc[w];
        }
        atomicAdd(&g_acc[0], (double)nlt);
        atomicAdd(&g_acc[1], (double)nnt);
        if (bc) {
            atomicAdd(&g_acc[2], (double)bx);
            atomicAdd(&g_acc[3], (double)ob);
            atomicAdd(&g_acc[4], (double)cs);
            atomicAdd(&g_acc[5], (double)bc);
        }
        __threadfence();
        unsigned old = atomicAdd(&g_done, 1u);
        if (old == (unsigned)(gridDim.x - 1)) {
            volatile double* vg = (volatile double*)g_acc;
            double no_l = vg[0] / fmax((double)vg[1], 1.0);
            double den  = fmax((double)vg[5], 1.0);
            double loss = 2.0 * (vg[2] / den) + vg[3] / den + no_l + vg[4] / den;
            out[0] = (float)loss;
            // reset for next graph replay
            vg[0] = 0.0; vg[1] = 0.0; vg[2] = 0.0; vg[3] = 0.0; vg[4] = 0.0; vg[5] = 0.0;
            __threadfence();
            g_done = 0u;
        }
    }
}

extern "C" void kernel_launch(void* const* d_in, const int* in_sizes, int n_in,
                              void* d_out, int out_size) {
    const float* pred = (const float*)d_in[0];
    const float* tgt  = (const float*)d_in[1];
    const float* anc  = (const float*)d_in[2];
    (void)in_sizes; (void)n_in; (void)out_size;
    k_fused<<<NBLK, TPB>>>(pred, tgt, anc, (float*)d_out);
}

// round 3
// speedup vs baseline: 1.6307x; 1.1915x over previous
#include <cuda_runtime.h>

namespace {
constexpr int A_ = 3, S_ = 80, NC_ = 80;
constexpr int NCELLS = 614400;
constexpr int TPB = 256;
constexpr int CPT = 4;                 // cells per thread
constexpr int CPB = TPB * CPT;         // 1024 cells per block
constexpr int NBLK = NCELLS / CPB;     // 600
constexpr float EPSF = 1e-7f;
constexpr float LSF  = 0.1f;
}

// 0 noobj_sum, 1 noobj_cnt, 2 box_sum, 3 obj_sum, 4 cls_sum, 5 obj_cnt
__device__ double       g_acc[6];
__device__ unsigned int g_done;

__global__ void __launch_bounds__(TPB, 5) k_fused(const float* __restrict__ pred,
                                                  const float* __restrict__ tgt,
                                                  const float* __restrict__ anchors,
                                                  float* __restrict__ out) {
    __shared__ float s_tgt[CPB * 6];        // 24 KB
    __shared__ int   s_obj[CPB];            // 4 KB
    __shared__ int   s_cnt;
    __shared__ float s_nl[8], s_box[8], s_objl[8], s_cls[8];
    __shared__ int   s_nn[8], s_bc[8];

    const int tid   = threadIdx.x;
    const int lane  = tid & 31;
    const int wib   = tid >> 5;
    const int cell0 = blockIdx.x * CPB;

    // ---- front-issued, independent objectness loads (MLP=4, L2-only) ----
    float z[CPT];
    {
        const float* p0 = pred + (size_t)cell0 * 85;
        #pragma unroll
        for (int c = 0; c < CPT; ++c)
            z[c] = __ldcg(p0 + (size_t)(tid + c * TPB) * 85);
    }
    if (tid == 0) s_cnt = 0;
    // ---- coalesced float4 staging of 1024 target rows (1536 float4) ----
    {
        const float4* gt4 = (const float4*)(tgt + (size_t)cell0 * 6);
        float4* st4 = (float4*)s_tgt;
        #pragma unroll
        for (int k = 0; k < 6; ++k) st4[tid + k * TPB] = gt4[tid + k * TPB];
    }
    __syncthreads();

    // ---- Phase A: no-object BCE + block-local compaction ----
    float nl = 0.0f;
    int   nn = 0;
    #pragma unroll
    for (int c = 0; c < CPT; ++c) {
        const int   cl = tid + c * TPB;
        const float t0 = s_tgt[cl * 6];
        const bool isno  = (t0 == 0.0f);
        const bool isobj = (t0 == 1.0f);
        if (isno) {
            nl += fmaxf(z[c], 0.0f) + __logf(1.0f + __expf(-fabsf(z[c])));
            nn += 1;
        }
        unsigned m = __ballot_sync(0xffffffffu, isobj);
        if (m) {
            int leader = __ffs(m) - 1;
            int base = 0;
            if (lane == leader) base = atomicAdd(&s_cnt, __popc(m));
            base = __shfl_sync(0xffffffffu, base, leader);
            if (isobj) s_obj[base + __popc(m & ((1u << lane) - 1u))] = cl;
        }
    }
    #pragma unroll
    for (int o = 16; o; o >>= 1) {
        nl += __shfl_xor_sync(0xffffffffu, nl, o);
        nn += __shfl_xor_sync(0xffffffffu, nn, o);
    }
    if (lane == 0) { s_nl[wib] = nl; s_nn[wib] = nn; }
    __syncthreads();

    // ---- Phase B: warp per object cell, software-pipelined ----
    const int nobj = s_cnt;
    float a_box = 0.0f, a_obj = 0.0f, a_cls = 0.0f;
    int   a_cnt = 0;

    int   w  = wib;
    int   cl = 0;
    float v0 = 0.0f, v1 = 0.0f, v2 = 0.0f;
    if (w < nobj) {
        cl = s_obj[w];
        const float* p = pred + (size_t)(cell0 + cl) * 85;
        v0 = p[lane];
        v1 = p[lane + 32];
        v2 = (lane < 21) ? p[lane + 64] : 0.0f;
    }
    while (w < nobj) {
        // prefetch next cell's row
        const int wn = w + 8;
        int   cln = 0;
        float n0 = 0.0f, n1 = 0.0f, n2 = 0.0f;
        if (wn < nobj) {
            cln = s_obj[wn];
            const float* pn = pred + (size_t)(cell0 + cln) * 85;
            n0 = pn[lane];
            n1 = pn[lane + 32];
            n2 = (lane < 21) ? pn[lane + 64] : 0.0f;
        }

        const float t1 = s_tgt[cl * 6 + 1];
        const float t2 = s_tgt[cl * 6 + 2];
        const float t3 = s_tgt[cl * 6 + 3];
        const float t4 = s_tgt[cl * 6 + 4];
        const int  tch = 5 + (int)s_tgt[cl * 6 + 5];   // warp-uniform

        // label-smoothed CE: logΣe − (1−LS)·logit_y − (LS/NC)·Σlogits
        float se = 0.0f, sl = 0.0f;
        if (lane >= 5) { se += __expf(v0); sl += v0; }
        {               se += __expf(v1); sl += v1; }
        if (lane < 21) { se += __expf(v2); sl += v2; }
        #pragma unroll
        for (int o = 16; o; o >>= 1) {
            se += __shfl_xor_sync(0xffffffffu, se, o);
            sl += __shfl_xor_sync(0xffffffffu, sl, o);
        }
        float yv;   // selected logit via single uniform-index shuffle
        if (tch < 32)      yv = __shfl_sync(0xffffffffu, v0, tch);
        else if (tch < 64) yv = __shfl_sync(0xffffffffu, v1, tch - 32);
        else               yv = __shfl_sync(0xffffffffu, v2, tch - 64);
        const float ce = __logf(se) - (1.0f - LSF) * yv - (LSF / (float)NC_) * sl;

        const float z0 = __shfl_sync(0xffffffffu, v0, 0);
        const float z1 = __shfl_sync(0xffffffffu, v0, 1);
        const float z2 = __shfl_sync(0xffffffffu, v0, 2);
        const float z3 = __shfl_sync(0xffffffffu, v0, 3);
        const float z4 = __shfl_sync(0xffffffffu, v0, 4);

        if (lane == 0) {
            const int cell = cell0 + cl;
            const int a = (cell / (S_ * S_)) % A_;
            const float aw = anchors[a * 2 + 0], ah = anchors[a * 2 + 1];
            const float px = 1.0f / (1.0f + __expf(-z1));
            const float py = 1.0f / (1.0f + __expf(-z2));
            const float pw = __expf(z3) * aw;
            const float ph = __expf(z4) * ah;
            const float x1a = px - pw * 0.5f, x1b = px + pw * 0.5f;
            const float y1a = py - ph * 0.5f, y1b = py + ph * 0.5f;
            const float x2a = t1 - t3 * 0.5f, x2b = t1 + t3 * 0.5f;
            const float y2a = t2 - t4 * 0.5f, y2b = t2 + t4 * 0.5f;
            const float iw = fmaxf(fminf(x1b, x2b) - fmaxf(x1a, x2a), 0.0f);
            const float ih = fmaxf(fminf(y1b, y2b) - fmaxf(y1a, y2a), 0.0f);
            const float inter = iw * ih;
            const float uni = pw * ph + t3 * t4 - inter + EPSF;
            const float iou = inter / uni;
            const float cw  = fmaxf(x1b, x2b) - fminf(x1a, x2a);
            const float chh = fmaxf(y1b, y2b) - fminf(y1a, y2a);
            const float c2  = cw * cw + chh * chh + EPSF;
            const float rho2 = (t1 - px) * (t1 - px) + (t2 - py) * (t2 - py);
            const float k4pi2 = 4.0f / (3.14159265358979323846f * 3.14159265358979323846f);
            const float dat = atanf(t3 / (t4 + EPSF)) - atanf(pw / (ph + EPSF));
            const float vv = k4pi2 * dat * dat;
            const float alpha = vv / (1.0f - iou + vv + EPSF);
            const float ciou = iou - rho2 / c2 - alpha * vv;
            a_box += 1.0f - ciou;
            const float s0 = 1.0f / (1.0f + __expf(-z0));  // quirk: sigmoid into BCE-logits
            a_obj += __logf(1.0f + __expf(-s0));           // s0>0: bce(s0,1) = log1p(exp(-s0))
            a_cls += ce;
            a_cnt += 1;
        }

        w = wn; cl = cln; v0 = n0; v1 = n1; v2 = n2;
    }

    if (lane == 0) { s_box[wib] = a_box; s_objl[wib] = a_obj; s_cls[wib] = a_cls; s_bc[wib] = a_cnt; }
    __syncthreads();

    // ---- block totals -> global atomics, last block finalizes ----
    if (tid == 0) {
        float nlt = 0.0f, bx = 0.0f, ob = 0.0f, cs = 0.0f;
        int nnt = 0, bc = 0;
        #pragma unroll
        for (int k = 0; k < 8; ++k) {
            nlt += s_nl[k]; nnt += s_nn[k];
            bx += s_box[k]; ob += s_objl[k]; cs += s_cls[k]; bc += s_bc[k];
        }
        atomicAdd(&g_acc[0], (double)nlt);
        atomicAdd(&g_acc[1], (double)nnt);
        if (bc) {
            atomicAdd(&g_acc[2], (double)bx);
            atomicAdd(&g_acc[3], (double)ob);
            atomicAdd(&g_acc[4], (double)cs);
            atomicAdd(&g_acc[5], (double)bc);
        }
        __threadfence();
        const unsigned old = atomicAdd(&g_done, 1u);
        if (old == (unsigned)(gridDim.x - 1)) {
            volatile double* vg = (volatile double*)g_acc;
            const double no_l = vg[0] / fmax((double)vg[1], 1.0);
            const double den  = fmax((double)vg[5], 1.0);
            const double loss = 2.0 * (vg[2] / den) + vg[3] / den + no_l + vg[4] / den;
            out[0] = (float)loss;
            vg[0] = 0.0; vg[1] = 0.0; vg[2] = 0.0; vg[3] = 0.0; vg[4] = 0.0; vg[5] = 0.0;
            __threadfence();
            g_done = 0u;
        }
    }
}

extern "C" void kernel_launch(void* const* d_in, const int* in_sizes, int n_in,
                              void* d_out, int out_size) {
    const float* pred = (const float*)d_in[0];
    const float* tgt  = (const float*)d_in[1];
    const float* anc  = (const float*)d_in[2];
    (void)in_sizes; (void)n_in; (void)out_size;
    k_fused<<<NBLK, TPB>>>(pred, tgt, anc, (float*)d_out);
}